// round 3
// baseline (speedup 1.0000x reference)
#include <cuda_runtime.h>

#define NN   50000
#define EE   500000
#define EMBD 50
#define C1   256
#define C2   50
#define ED   28
#define TE   16

static __device__ float  g_xl[(size_t)NN * C1];
static __device__ float  g_xr[(size_t)NN * C1];
static __device__ float  g_h1[(size_t)NN * C1];
static __device__ float  g_logit[(size_t)EE * 4];
static __device__ float  g_max[(size_t)5 * NN];
static __device__ float  g_den[(size_t)5 * NN];
static __device__ int    g_off[NN + 1];
static __device__ int    g_cur[NN];
static __device__ int    g_eid[EE];
static __device__ int    g_esrc[EE];
static __device__ float  g_o2[(size_t)NN * C2];
static __device__ double g_red[4];

__device__ __forceinline__ float lrelu(float v) { return v > 0.f ? v : 0.2f * v; }

__device__ __forceinline__ void atomicMaxF(float* a, float v) {
    if (!(__float_as_uint(v) >> 31)) atomicMax((int*)a, __float_as_int(v));
    else                             atomicMin((unsigned int*)a, __float_as_uint(v));
}

__global__ void k_init() {
    int i = blockIdx.x * blockDim.x + threadIdx.x;
    if (i < 5 * NN) { g_max[i] = __int_as_float(0xFF800000); g_den[i] = 0.f; }
    if (i < NN) g_cur[i] = 0;
    if (i < 4)  g_red[i] = 0.0;
}

__global__ void k_deg(const int* __restrict__ ei) {
    int e = blockIdx.x * blockDim.x + threadIdx.x;
    if (e < EE) atomicAdd(&g_cur[ei[EE + e]], 1);
}

__global__ void k_scan() {
    __shared__ int sh[1024];
    __shared__ int carry_s;
    int t = threadIdx.x;
    if (t == 0) carry_s = 0;
    __syncthreads();
    for (int base = 0; base < NN; base += 1024) {
        int i = base + t;
        int v = (i < NN) ? g_cur[i] : 0;
        int x = v;
        sh[t] = x; __syncthreads();
        for (int off = 1; off < 1024; off <<= 1) {
            int y = (t >= off) ? sh[t - off] : 0;
            __syncthreads();
            x += y; sh[t] = x; __syncthreads();
        }
        int carry = carry_s;
        if (i < NN) g_off[i] = carry + x - v;
        __syncthreads();
        if (t == 1023) carry_s = carry + x;
        __syncthreads();
    }
    if (t == 0) g_off[NN] = carry_s;
    __syncthreads();
    for (int i = t; i < NN; i += 1024) g_cur[i] = g_off[i];
}

__global__ void k_fill(const int* __restrict__ ei) {
    int e = blockIdx.x * blockDim.x + threadIdx.x;
    if (e < EE) {
        int d = ei[EE + e];
        int pos = atomicAdd(&g_cur[d], 1);
        g_eid[pos]  = e;
        g_esrc[pos] = ei[e];
    }
}

__global__ void k_node1(const int* __restrict__ x, const float* __restrict__ emb,
                        const float* __restrict__ Wl, const float* __restrict__ bl,
                        const float* __restrict__ Wr, const float* __restrict__ br) {
    __shared__ float hs[4][EMBD];
    __shared__ int xs[4];
    int t = threadIdx.x;                       // 64 threads
    int nb = blockIdx.x * 4;
    if (t < 4) xs[t] = x[nb + t];
    __syncthreads();
    for (int i = t; i < 4 * EMBD; i += 64) {
        int n = i / EMBD, k = i % EMBD;
        hs[n][k] = emb[(size_t)xs[n] * EMBD + k];
    }
    __syncthreads();
    int c0 = t * 4;
    float4 blv = *(const float4*)&bl[c0];
    float4 brv = *(const float4*)&br[c0];
    float4 al[4], ar[4];
#pragma unroll
    for (int n = 0; n < 4; n++) { al[n] = blv; ar[n] = brv; }
    for (int k = 0; k < EMBD; k++) {
        float4 wl = *(const float4*)&Wl[k * C1 + c0];
        float4 wr = *(const float4*)&Wr[k * C1 + c0];
#pragma unroll
        for (int n = 0; n < 4; n++) {
            float h = hs[n][k];
            al[n].x += h * wl.x; al[n].y += h * wl.y; al[n].z += h * wl.z; al[n].w += h * wl.w;
            ar[n].x += h * wr.x; ar[n].y += h * wr.y; ar[n].z += h * wr.z; ar[n].w += h * wr.w;
        }
    }
#pragma unroll
    for (int n = 0; n < 4; n++) {
        *(float4*)&g_xl[(size_t)(nb + n) * C1 + c0] = al[n];
        *(float4*)&g_xr[(size_t)(nb + n) * C1 + c0] = ar[n];
    }
}

__global__ __launch_bounds__(256) void k_edge1(const int* __restrict__ ei,
                                               const float* __restrict__ ea,
                                               const float* __restrict__ We,
                                               const float* __restrict__ att) {
    __shared__ float s_we[ED * C1];
    __shared__ float s_m[TE][C1];
    __shared__ float s_ea[TE][ED];
    __shared__ int s_src[TE], s_dst[TE];
    int t  = threadIdx.x;
    int eb = blockIdx.x * TE;
    if (t < TE) { s_src[t] = ei[eb + t]; s_dst[t] = ei[EE + eb + t]; }
    for (int i = t; i < TE * ED; i += 256) {
        int e = i / ED, k = i % ED;
        s_ea[e][k] = ea[(size_t)(eb + e) * ED + k];
    }
    for (int i = t; i < ED * C1 / 4; i += 256)
        ((float4*)s_we)[i] = ((const float4*)We)[i];
    __syncthreads();
    for (int i = t; i < TE * C1 / 4; i += 256) {
        int e  = i >> 6;
        int c4 = (i & 63) * 4;
        float4 a = *(const float4*)&g_xl[(size_t)s_src[e] * C1 + c4];
        float4 b = *(const float4*)&g_xr[(size_t)s_dst[e] * C1 + c4];
        a.x += b.x; a.y += b.y; a.z += b.z; a.w += b.w;
        *(float4*)&s_m[e][c4] = a;
    }
    __syncthreads();
    int cg = t & 63, eq = t >> 6;
    int c0 = cg * 4;
    float4 acc[4];
#pragma unroll
    for (int j = 0; j < 4; j++) acc[j] = *(const float4*)&s_m[eq * 4 + j][c0];
#pragma unroll
    for (int k = 0; k < ED; k++) {
        float4 w = *(const float4*)&s_we[k * C1 + c0];
#pragma unroll
        for (int j = 0; j < 4; j++) {
            float a = s_ea[eq * 4 + j][k];
            acc[j].x += a * w.x; acc[j].y += a * w.y; acc[j].z += a * w.z; acc[j].w += a * w.w;
        }
    }
    float a0 = att[c0], a1 = att[c0 + 1], a2 = att[c0 + 2], a3 = att[c0 + 3];
    float part[4];
#pragma unroll
    for (int j = 0; j < 4; j++)
        part[j] = lrelu(acc[j].x) * a0 + lrelu(acc[j].y) * a1 +
                  lrelu(acc[j].z) * a2 + lrelu(acc[j].w) * a3;
#pragma unroll
    for (int off = 8; off; off >>= 1) {
#pragma unroll
        for (int j = 0; j < 4; j++)
            part[j] += __shfl_down_sync(0xffffffffu, part[j], off);
    }
    int lane = t & 31;
    if ((lane & 15) == 0) {
        int h = cg >> 4;
#pragma unroll
        for (int j = 0; j < 4; j++) {
            int e = eq * 4 + j;
            g_logit[(size_t)(eb + e) * 4 + h] = part[j];
            atomicMaxF(&g_max[s_dst[e] * 4 + h], part[j]);
        }
    }
}

__global__ void k_ex1(const int* __restrict__ ei) {
    int i = blockIdx.x * blockDim.x + threadIdx.x;
    if (i < EE * 4) {
        int e = i >> 2, h = i & 3;
        int d = ei[EE + e];
        float ex = expf(g_logit[i] - g_max[d * 4 + h]);
        g_logit[i] = ex;
        atomicAdd(&g_den[d * 4 + h], ex);
    }
}

__global__ void k_agg1(const float* __restrict__ bias) {
    int n = blockIdx.x;
    int t = threadIdx.x;                      // 64 threads
    int c0 = t * 4;
    int h  = t >> 4;
    int s = g_off[n], en = g_off[n + 1];
    float4 acc = make_float4(0.f, 0.f, 0.f, 0.f);
    for (int p = s; p < en; p++) {
        int eid = g_eid[p];
        int src = g_esrc[p];
        float ex = g_logit[(size_t)eid * 4 + h];
        float4 v = *(const float4*)&g_xl[(size_t)src * C1 + c0];
        acc.x += ex * v.x; acc.y += ex * v.y; acc.z += ex * v.z; acc.w += ex * v.w;
    }
    float inv = 1.f / (g_den[n * 4 + h] + 1e-16f);
    float4 bv = *(const float4*)&bias[c0];
    float4 o;
    o.x = acc.x * inv + bv.x; o.y = acc.y * inv + bv.y;
    o.z = acc.z * inv + bv.z; o.w = acc.w * inv + bv.w;
    *(float4*)&g_h1[(size_t)n * C1 + c0] = o;
}

__device__ void stats_body(const float* buf, int n, int slot) {
    long long stride = (long long)gridDim.x * blockDim.x;
    double s = 0.0, q = 0.0;
    for (long long i = (long long)blockIdx.x * blockDim.x + threadIdx.x; i < n; i += stride) {
        double v = buf[i]; s += v; q += v * v;
    }
#pragma unroll
    for (int off = 16; off; off >>= 1) {
        s += __shfl_down_sync(0xffffffffu, s, off);
        q += __shfl_down_sync(0xffffffffu, q, off);
    }
    __shared__ double sh[8], qh[8];
    int lane = threadIdx.x & 31, w = threadIdx.x >> 5;
    if (lane == 0) { sh[w] = s; qh[w] = q; }
    __syncthreads();
    if (threadIdx.x < 32) {
        s = (lane < 8) ? sh[lane] : 0.0;
        q = (lane < 8) ? qh[lane] : 0.0;
#pragma unroll
        for (int off = 4; off; off >>= 1) {
            s += __shfl_down_sync(0xffffffffu, s, off);
            q += __shfl_down_sync(0xffffffffu, q, off);
        }
        if (lane == 0) { atomicAdd(&g_red[slot], s); atomicAdd(&g_red[slot + 1], q); }
    }
}
__global__ void k_stats1() { stats_body(g_h1, NN * C1, 0); }
__global__ void k_stats2() { stats_body(g_o2, NN * C2, 2); }

__global__ void k_ln1(const float* __restrict__ w, const float* __restrict__ b) {
    int i = blockIdx.x * blockDim.x + threadIdx.x;
    if (i < NN * C1) {
        double M = (double)NN * C1;
        double mean = g_red[0] / M;
        double var  = g_red[1] / M - mean * mean;
        float f = 1.f / ((float)sqrt(var > 0.0 ? var : 0.0) + 1e-5f);
        int c = i & (C1 - 1);
        float v = (g_h1[i] - (float)mean) * f * w[c] + b[c];
        g_h1[i] = v > 0.f ? v : 0.f;
    }
}

__global__ void k_node2(const float* __restrict__ Wl, const float* __restrict__ bl,
                        const float* __restrict__ Wr, const float* __restrict__ br) {
    __shared__ float hs[16][C1];
    int t = threadIdx.x;                      // 64 threads
    int nb = blockIdx.x * 16;
    for (int i = t; i < 16 * C1 / 4; i += 64)
        ((float4*)hs)[i] = *(const float4*)&g_h1[(size_t)nb * C1 + (size_t)i * 4];
    __syncthreads();
    bool act = t < C2;
    float accl[16], accr[16];
    float blv = act ? bl[t] : 0.f, brv = act ? br[t] : 0.f;
#pragma unroll
    for (int j = 0; j < 16; j++) { accl[j] = blv; accr[j] = brv; }
    for (int k = 0; k < C1; k += 4) {
        float wl0 = 0, wl1 = 0, wl2 = 0, wl3 = 0, wr0 = 0, wr1 = 0, wr2 = 0, wr3 = 0;
        if (act) {
            wl0 = Wl[k * C2 + t]; wl1 = Wl[(k + 1) * C2 + t];
            wl2 = Wl[(k + 2) * C2 + t]; wl3 = Wl[(k + 3) * C2 + t];
            wr0 = Wr[k * C2 + t]; wr1 = Wr[(k + 1) * C2 + t];
            wr2 = Wr[(k + 2) * C2 + t]; wr3 = Wr[(k + 3) * C2 + t];
        }
#pragma unroll
        for (int j = 0; j < 16; j++) {
            float4 hv = *(const float4*)&hs[j][k];
            accl[j] += hv.x * wl0 + hv.y * wl1 + hv.z * wl2 + hv.w * wl3;
            accr[j] += hv.x * wr0 + hv.y * wr1 + hv.z * wr2 + hv.w * wr3;
        }
    }
    if (act) {
#pragma unroll
        for (int j = 0; j < 16; j++) {
            g_xl[(size_t)(nb + j) * C2 + t] = accl[j];
            g_xr[(size_t)(nb + j) * C2 + t] = accr[j];
        }
    }
}

__global__ __launch_bounds__(256) void k_edge2(const int* __restrict__ ei,
                                               const float* __restrict__ ea,
                                               const float* __restrict__ We,
                                               const float* __restrict__ att) {
    int lane = threadIdx.x & 31;
    int gw = (blockIdx.x * blockDim.x + threadIdx.x) >> 5;
    int nw = (gridDim.x * blockDim.x) >> 5;
    int c0 = lane * 2;
    bool act = c0 < C2;
    float2 w[ED];
#pragma unroll
    for (int k = 0; k < ED; k++)
        w[k] = act ? *(const float2*)&We[k * C2 + c0] : make_float2(0.f, 0.f);
    float2 a2 = act ? *(const float2*)&att[c0] : make_float2(0.f, 0.f);
    for (int e = gw; e < EE; e += nw) {
        int src = ei[e], dst = ei[EE + e];
        float eav = (lane < ED) ? ea[(size_t)e * ED + lane] : 0.f;
        float mx = 0.f, my = 0.f;
        if (act) {
            float2 u = *(const float2*)&g_xl[(size_t)src * C2 + c0];
            float2 v = *(const float2*)&g_xr[(size_t)dst * C2 + c0];
            mx = u.x + v.x; my = u.y + v.y;
        }
#pragma unroll
        for (int k = 0; k < ED; k++) {
            float a = __shfl_sync(0xffffffffu, eav, k);
            mx += a * w[k].x; my += a * w[k].y;
        }
        float p = lrelu(mx) * a2.x + lrelu(my) * a2.y;
#pragma unroll
        for (int off = 16; off; off >>= 1) p += __shfl_down_sync(0xffffffffu, p, off);
        if (lane == 0) {
            g_logit[e] = p;
            atomicMaxF(&g_max[4 * NN + dst], p);
        }
    }
}

__global__ void k_ex2(const int* __restrict__ ei) {
    int e = blockIdx.x * blockDim.x + threadIdx.x;
    if (e < EE) {
        int d = ei[EE + e];
        float ex = expf(g_logit[e] - g_max[4 * NN + d]);
        g_logit[e] = ex;
        atomicAdd(&g_den[4 * NN + d], ex);
    }
}

__global__ void k_agg2(const float* __restrict__ bias) {
    int n = blockIdx.x;
    int t = threadIdx.x;                      // 64 threads, 50 active
    int s = g_off[n], en = g_off[n + 1];
    bool act = t < C2;
    float acc = 0.f;
    for (int p = s; p < en; p++) {
        int src = g_esrc[p];
        float ex = g_logit[g_eid[p]];
        if (act) acc += ex * g_xl[(size_t)src * C2 + t];
    }
    if (act) {
        float inv = 1.f / (g_den[4 * NN + n] + 1e-16f);
        g_o2[(size_t)n * C2 + t] = acc * inv + bias[t];
    }
}

__global__ void k_ln2(float* __restrict__ out, const float* __restrict__ w,
                      const float* __restrict__ b) {
    int i = blockIdx.x * blockDim.x + threadIdx.x;
    if (i < NN * C2) {
        double M = (double)NN * C2;
        double mean = g_red[2] / M;
        double var  = g_red[3] / M - mean * mean;
        float f = 1.f / ((float)sqrt(var > 0.0 ? var : 0.0) + 1e-5f);
        int c = i % C2;
        out[i] = (g_o2[i] - (float)mean) * f * w[c] + b[c];
    }
}

extern "C" void kernel_launch(void* const* d_in, const int* in_sizes, int n_in,
                              void* d_out, int out_size) {
    const int*   x    = (const int*)d_in[0];
    const int*   ei   = (const int*)d_in[1];
    const float* ea   = (const float*)d_in[2];
    const float* emb  = (const float*)d_in[3];
    const float* Wl1  = (const float*)d_in[4];
    const float* bl1  = (const float*)d_in[5];
    const float* Wr1  = (const float*)d_in[6];
    const float* br1  = (const float*)d_in[7];
    const float* We1  = (const float*)d_in[8];
    const float* att1 = (const float*)d_in[9];
    const float* bias1= (const float*)d_in[10];
    const float* ln1w = (const float*)d_in[11];
    const float* ln1b = (const float*)d_in[12];
    const float* Wl2  = (const float*)d_in[13];
    const float* bl2  = (const float*)d_in[14];
    const float* Wr2  = (const float*)d_in[15];
    const float* br2  = (const float*)d_in[16];
    const float* We2  = (const float*)d_in[17];
    const float* att2 = (const float*)d_in[18];
    const float* bias2= (const float*)d_in[19];
    const float* ln2w = (const float*)d_in[20];
    const float* ln2b = (const float*)d_in[21];
    float* out = (float*)d_out;

    k_init<<<(5 * NN + 255) / 256, 256>>>();
    k_deg<<<(EE + 255) / 256, 256>>>(ei);
    k_scan<<<1, 1024>>>();
    k_fill<<<(EE + 255) / 256, 256>>>(ei);
    k_node1<<<NN / 4, 64>>>(x, emb, Wl1, bl1, Wr1, br1);
    k_edge1<<<EE / TE, 256>>>(ei, ea, We1, att1);
    k_ex1<<<(EE * 4 + 255) / 256, 256>>>(ei);
    k_agg1<<<NN, 64>>>(bias1);
    k_stats1<<<1024, 256>>>();
    k_ln1<<<(NN * C1 + 255) / 256, 256>>>(ln1w, ln1b);
    k_node2<<<NN / 16, 64>>>(Wl2, bl2, Wr2, br2);
    k_edge2<<<1024, 256>>>(ei, ea, We2, att2);
    k_ex2<<<(EE + 255) / 256, 256>>>(ei);
    k_agg2<<<NN, 64>>>(bias2);
    k_stats2<<<1024, 256>>>();
    k_ln2<<<(NN * C2 + 255) / 256, 256>>>(out, ln2w, ln2b);
}